// round 4
// baseline (speedup 1.0000x reference)
#include <cuda_runtime.h>
#include <math.h>

#define BB 8
#define NN1 64
#define NN2 512
#define DD 128
#define NL 3
#define NT 7
#define R1T (BB*NN1)            // 512
#define R2T (BB*NN2)            // 4096
#define RTOT (R1T+R2T)          // 4608
#define CAP 96
#define NBLK 256
#define NTH 256
#define NWARP ((NBLK*NTH)/32)   // 2048

// ---------------- scratch ----------------
__device__ __align__(16) float g_x  [RTOT*DD];
__device__ __align__(16) float g_hc [RTOT*256];
__device__ __align__(16) float g_e1 [BB*NN1*NN1];
__device__ __align__(16) float g_e2 [BB*NN2*NN2];
__device__ __align__(16) float g_wc [NL*DD*256];
__device__ __align__(16) float g_bc [NL*256];
__device__ __align__(16) float g_u1 [14*R1T*DD];
__device__ __align__(16) float g_u2 [14*R2T*DD];
__device__ unsigned char g_mask[BB*NN1*NN2];
__device__ float g_partial[BB*NBLK*NT];
__device__ int   g_rl[RTOT*CAP];
__device__ int   g_rcnt[RTOT];
__device__ float g_mx[RTOT];
__device__ float g_zi[RTOT];
__device__ unsigned g_bar_count = 0;
__device__ unsigned g_bar_gen = 0;

__constant__ float BCON[7] = {1.159f,0.448f,0.927f,0.902f,0.349f,0.789f,0.198f};

// ---------------- software grid barrier (all NBLK blocks co-resident) ----------------
__device__ __forceinline__ void grid_sync()
{
    __syncthreads();
    if (threadIdx.x == 0) {
        __threadfence();
        unsigned gen = *((volatile unsigned*)&g_bar_gen);
        if (atomicAdd(&g_bar_count, 1u) == NBLK - 1u) {
            atomicExch(&g_bar_count, 0u);
            __threadfence();
            atomicExch(&g_bar_gen, gen + 1u);
        } else {
            while (*((volatile unsigned*)&g_bar_gen) == gen) __nanosleep(32);
        }
        __threadfence();
    }
    __syncthreads();
}

// ---------------- 32x128 tile GEMM, 4x4 micro, K guarded ----------------
__device__ __forceinline__ void gemm32_tile(
    const float* __restrict__ A, int lda, int K,
    const float* __restrict__ B, int ldb,
    const float* __restrict__ bias,
    float* __restrict__ C, int ldc,
    float* As /*32x36*/, float* Bs /*32x128*/)
{
    int t = threadIdx.x, rq = t >> 5, cq = t & 31;
    float acc[4][4];
#pragma unroll
    for (int i = 0; i < 4; i++)
#pragma unroll
        for (int j = 0; j < 4; j++) acc[i][j] = 0.f;
    for (int k0 = 0; k0 < K; k0 += 32) {
#pragma unroll
        for (int s = 0; s < 4; s++) {
            int i = t + 256 * s, r = i >> 5, kk = i & 31, gk = k0 + kk;
            As[kk * 36 + r] = (gk < K) ? A[r * lda + gk] : 0.f;
        }
#pragma unroll
        for (int s = 0; s < 16; s++) {
            int i = t + 256 * s, kk = i >> 7, c = i & 127, gk = k0 + kk;
            Bs[kk * 128 + c] = (gk < K) ? B[gk * ldb + c] : 0.f;
        }
        __syncthreads();
#pragma unroll
        for (int kk = 0; kk < 32; kk++) {
            float4 av = *(const float4*)&As[kk * 36 + rq * 4];
            float4 bv = *(const float4*)&Bs[kk * 128 + cq * 4];
            float ar[4] = {av.x, av.y, av.z, av.w};
            float br[4] = {bv.x, bv.y, bv.z, bv.w};
#pragma unroll
            for (int i = 0; i < 4; i++)
#pragma unroll
                for (int j = 0; j < 4; j++) acc[i][j] += ar[i] * br[j];
        }
        __syncthreads();
    }
    float4 bvv = make_float4(0.f, 0.f, 0.f, 0.f);
    if (bias) bvv = *(const float4*)&bias[cq * 4];
#pragma unroll
    for (int i = 0; i < 4; i++) {
        float4 o;
        o.x = acc[i][0] + bvv.x; o.y = acc[i][1] + bvv.y;
        o.z = acc[i][2] + bvv.z; o.w = acc[i][3] + bvv.w;
        *(float4*)&C[(rq * 4 + i) * ldc + cq * 4] = o;
    }
}

// ---------------- 64x128 tile GEMM, 8x4 micro, K=128 ----------------
__device__ __forceinline__ void gemm64_tile(
    const float* __restrict__ A, int lda,
    const float* __restrict__ B, int ldb,
    const float* __restrict__ bias,
    float* __restrict__ C, int ldc,
    float* As /*32x68*/, float* Bs /*32x128*/)
{
    int t = threadIdx.x, w = t >> 5, lane = t & 31;
    float acc[8][4];
#pragma unroll
    for (int i = 0; i < 8; i++)
#pragma unroll
        for (int j = 0; j < 4; j++) acc[i][j] = 0.f;
    for (int k0 = 0; k0 < 128; k0 += 32) {
#pragma unroll
        for (int s = 0; s < 8; s++) {
            int i = t + 256 * s, r = i >> 5, kk = i & 31;
            As[kk * 68 + r] = A[r * lda + k0 + kk];
        }
#pragma unroll
        for (int s = 0; s < 16; s++) {
            int i = t + 256 * s, kk = i >> 7, c = i & 127;
            Bs[kk * 128 + c] = B[(k0 + kk) * ldb + c];
        }
        __syncthreads();
#pragma unroll
        for (int kk = 0; kk < 32; kk++) {
            float4 a0 = *(const float4*)&As[kk * 68 + w * 8];
            float4 a1 = *(const float4*)&As[kk * 68 + w * 8 + 4];
            float4 bv = *(const float4*)&Bs[kk * 128 + lane * 4];
            float ar[8] = {a0.x, a0.y, a0.z, a0.w, a1.x, a1.y, a1.z, a1.w};
            float br[4] = {bv.x, bv.y, bv.z, bv.w};
#pragma unroll
            for (int i = 0; i < 8; i++)
#pragma unroll
                for (int j = 0; j < 4; j++) acc[i][j] += ar[i] * br[j];
        }
        __syncthreads();
    }
    float4 bvv = make_float4(0.f, 0.f, 0.f, 0.f);
    if (bias) bvv = *(const float4*)&bias[lane * 4];
#pragma unroll
    for (int i = 0; i < 8; i++) {
        float4 o;
        o.x = acc[i][0] + bvv.x; o.y = acc[i][1] + bvv.y;
        o.z = acc[i][2] + bvv.z; o.w = acc[i][3] + bvv.w;
        *(float4*)&C[(w * 8 + i) * ldc + lane * 4] = o;
    }
}

// ---------------- the mega kernel ----------------
__global__ void __launch_bounds__(NTH, 2) mega(
    const float* __restrict__ h1, const float* __restrict__ adj1,
    const float* __restrict__ h2, const float* __restrict__ adj2,
    const float* __restrict__ A_int, const float* __restrict__ dmv,
    const float* __restrict__ valid, const float* __restrict__ W_embed,
    const float* __restrict__ gW, const float* __restrict__ gWb,
    const float* __restrict__ gA, const float* __restrict__ gGateW,
    const float* __restrict__ gGateb,
    const float* __restrict__ WA1, const float* __restrict__ bA1,
    const float* __restrict__ WA2, const float* __restrict__ bA2,
    const float* __restrict__ WB1, const float* __restrict__ bB1,
    const float* __restrict__ WB2, const float* __restrict__ bB2,
    const float* __restrict__ Cw,
    const float* __restrict__ Wi1, const float* __restrict__ bi1,
    const float* __restrict__ Wi2, const float* __restrict__ bi2,
    float* __restrict__ out)
{
    __shared__ __align__(16) float shA[32 * 68];    // 8704 B
    __shared__ __align__(16) float shB[32 * 128];   // 16384 B
    const int t = threadIdx.x;
    const int lane = t & 31;
    const int gtid = blockIdx.x * NTH + t;
    const int wgid = gtid >> 5;

    // ================= P0: prep (all independent) =================
    // (a) combined GAT weights: Wc=[W | W@A], bc=[Wb | Wb@A]
    if (gtid < NL * DD * DD) {
        int c = gtid & 127, d = (gtid >> 7) & 127, l = gtid >> 14;
        const float* W = gW + l * DD * DD;
        const float* Am = gA + l * DD * DD;
        g_wc[(l * DD + d) * 256 + c] = W[d * DD + c];
        float s = 0.f;
#pragma unroll 8
        for (int dd = 0; dd < DD; dd++) s += W[d * DD + dd] * Am[dd * DD + c];
        g_wc[(l * DD + d) * 256 + 128 + c] = s;
        if (d == 0) {
            g_bc[l * 256 + c] = gWb[l * DD + c];
            float sb = 0.f;
#pragma unroll 8
            for (int dd = 0; dd < DD; dd++) sb += gWb[l * DD + dd] * Am[dd * DD + c];
            g_bc[l * 256 + 128 + c] = sb;
        }
    }
    // (b) row adjacency lists (order-preserving, deterministic)
    for (int row = wgid; row < RTOT; row += NWARP) {
        const float* aj; int N;
        if (row < R1T) { int b = row >> 6, r = row & 63; N = NN1; aj = adj1 + (b * NN1 + r) * NN1; }
        else { int rr = row - R1T; int b = rr >> 9, r = rr & 511; N = NN2; aj = adj2 + (b * NN2 + r) * NN2; }
        int cnt = 0;
        for (int base = 0; base < N; base += 32) {
            int c = base + lane;
            bool v = (aj[c] != 0.f);
            unsigned m = __ballot_sync(0xffffffffu, v);
            if (v) {
                int pos = cnt + __popc(m & ((1u << lane) - 1u));
                if (pos < CAP) g_rl[row * CAP + pos] = c;
            }
            cnt += __popc(m);
        }
        if (cnt > CAP) cnt = CAP;
        if (lane == 0) g_rcnt[row] = cnt;
    }
    // (c) pack A_int into 7-bit masks
    for (int p = gtid; p < BB * NN1 * NN2; p += NBLK * NTH) {
        int k = p & 511, j = (p >> 9) & 63, b = p >> 15;
        unsigned m = 0;
#pragma unroll
        for (int i = 0; i < 7; i++)
            if (A_int[((b * 7 + i) * NN1 + j) * NN2 + k] != 0.f) m |= 1u << i;
        g_mask[p] = (unsigned char)m;
    }
    // (d) embedding: x = h @ W_embed   (144 tiles of 32x128, K=56)
    for (int tile = blockIdx.x; tile < RTOT / 32; tile += NBLK) {
        int row0 = tile * 32;
        const float* Ap = (row0 < R1T) ? (h1 + row0 * 56) : (h2 + (row0 - R1T) * 56);
        gemm32_tile(Ap, 56, 56, W_embed, 128, nullptr, g_x + row0 * 128, 128, shA, shB);
    }
    grid_sync();

    // ================= GAT layers =================
    for (int l = 0; l < NL; l++) {
        // A: hc = x @ Wc + bc   (288 tiles of 32x128)
        for (int tile = blockIdx.x; tile < 288; tile += NBLK) {
            int rowtile = tile >> 1, colb = tile & 1;
            gemm32_tile(g_x + rowtile * 32 * 128, 128, 128,
                        g_wc + l * DD * 256 + colb * 128, 256,
                        g_bc + l * 256 + colb * 128,
                        g_hc + rowtile * 32 * 256 + colb * 128, 256, shA, shB);
        }
        grid_sync();
        // B: sparse e at adjacency positions
        for (int row = wgid; row < RTOT; row += NWARP) {
            int N, r, gbase; float* E;
            if (row < R1T) { int b = row >> 6; r = row & 63; N = NN1; gbase = b * NN1; E = g_e1 + b * NN1 * NN1; }
            else { int rr = row - R1T; int b = rr >> 9; r = rr & 511; N = NN2; gbase = R1T + b * NN2; E = g_e2 + b * NN2 * NN2; }
            float4 hr  = *(const float4*)&g_hc[row * 256 + lane * 4];
            float4 har = *(const float4*)&g_hc[row * 256 + 128 + lane * 4];
            int cnt = g_rcnt[row];
            const int* rl = g_rl + row * CAP;
            for (int idx = 0; idx < cnt; idx++) {
                int c = rl[idx];
                int grow = gbase + c;
                float4 hv  = *(const float4*)&g_hc[grow * 256 + lane * 4];
                float4 hav = *(const float4*)&g_hc[grow * 256 + 128 + lane * 4];
                float p = har.x * hv.x + har.y * hv.y + har.z * hv.z + har.w * hv.w
                        + hr.x * hav.x + hr.y * hav.y + hr.z * hav.z + hr.w * hav.w;
#pragma unroll
                for (int o = 16; o; o >>= 1) p += __shfl_xor_sync(0xffffffffu, p, o);
                if (lane == 0) E[r * N + c] = p;
            }
        }
        grid_sync();
        // C: masked column softmax stats (144 strips of 32 columns)
        for (int s = blockIdx.x; s < 144; s += NBLK) {
            int N, c0, gbase;
            const float* aj; const float* E;
            if (s < 16) {
                int b = s >> 1; N = NN1; c0 = (s & 1) * 32; gbase = b * NN1;
                aj = adj1 + b * NN1 * NN1; E = g_e1 + b * NN1 * NN1;
            } else {
                int s2 = s - 16; int b = s2 >> 4; N = NN2; c0 = (s2 & 15) * 32; gbase = R1T + b * NN2;
                aj = adj2 + b * NN2 * NN2; E = g_e2 + b * NN2 * NN2;
            }
            int col = t & 31, ro = t >> 5;
            int c = c0 + col;
            float* red = shA;   // [8][33]
            float mx = -1e30f;
            for (int r = ro; r < N; r += 8)
                if (aj[r * N + c] > 0.f) mx = fmaxf(mx, E[r * N + c]);
            red[ro * 33 + col] = mx;
            __syncthreads();
            float mcol = 0.f;
            if (t < 32) {
                float m = red[col];
#pragma unroll
                for (int q = 1; q < 8; q++) m = fmaxf(m, red[q * 33 + col]);
                red[col] = m;
            }
            __syncthreads();
            mcol = red[col];
            __syncthreads();
            float sm = 0.f;
            for (int r = ro; r < N; r += 8)
                if (aj[r * N + c] > 0.f) sm += expf(E[r * N + c] - mcol);
            red[ro * 33 + col] = sm;
            __syncthreads();
            if (t < 32) {
                float ssum = red[col];
#pragma unroll
                for (int q = 1; q < 8; q++) ssum += red[q * 33 + col];
                g_mx[gbase + c] = mcol;
                g_zi[gbase + c] = 1.f / ssum;
            }
            __syncthreads();
        }
        grid_sync();
        // D: sparse att@h + relu + gate, fused
        {
            const float* Wg = gGateW + l * 256;
            float bg0 = gGateb[l];
            for (int row = wgid; row < RTOT; row += NWARP) {
                int N, r, gbase; const float* E;
                if (row < R1T) { int b = row >> 6; r = row & 63; N = NN1; gbase = b * NN1; E = g_e1 + b * NN1 * NN1; }
                else { int rr = row - R1T; int b = rr >> 9; r = rr & 511; N = NN2; gbase = R1T + b * NN2; E = g_e2 + b * NN2 * NN2; }
                float4 acc = make_float4(0.f, 0.f, 0.f, 0.f);
                int cnt = g_rcnt[row];
                const int* rl = g_rl + row * CAP;
                for (int idx = 0; idx < cnt; idx++) {
                    int c = rl[idx];
                    int grow = gbase + c;
                    float wv = expf(E[r * N + c] - g_mx[grow]) * g_zi[grow];
                    float4 hv = *(const float4*)&g_hc[grow * 256 + lane * 4];
                    acc.x += wv * hv.x; acc.y += wv * hv.y; acc.z += wv * hv.z; acc.w += wv * hv.w;
                }
                float hp[4] = {fmaxf(acc.x, 0.f), fmaxf(acc.y, 0.f), fmaxf(acc.z, 0.f), fmaxf(acc.w, 0.f)};
                float4 xv4 = *(const float4*)&g_x[row * 128 + lane * 4];
                float xv[4] = {xv4.x, xv4.y, xv4.z, xv4.w};
                float4 wx4 = *(const float4*)&Wg[lane * 4];
                float4 wh4 = *(const float4*)&Wg[128 + lane * 4];
                float p = xv[0] * wx4.x + xv[1] * wx4.y + xv[2] * wx4.z + xv[3] * wx4.w
                        + hp[0] * wh4.x + hp[1] * wh4.y + hp[2] * wh4.z + hp[3] * wh4.w;
#pragma unroll
                for (int o = 16; o; o >>= 1) p += __shfl_xor_sync(0xffffffffu, p, o);
                float cf = 1.f / (1.f + expf(-(p + bg0)));
                float4 ov;
                ov.x = cf * xv[0] + (1.f - cf) * hp[0];
                ov.y = cf * xv[1] + (1.f - cf) * hp[1];
                ov.z = cf * xv[2] + (1.f - cf) * hp[2];
                ov.w = cf * xv[3] + (1.f - cf) * hp[3];
                *(float4*)&g_x[row * 128 + lane * 4] = ov;
            }
        }
        grid_sync();
    }

    // ================= E: u GEMMs (1008 tiles of 64x128, K=128) =================
    for (int tile = blockIdx.x; tile < 1008; tile += NBLK) {
        const float* Ap; const float* Bp; const float* bp = nullptr; float* Cp;
        if (tile < 112) {
            int z = tile >> 3, rt = tile & 7;
            Ap = g_x + rt * 64 * 128;
            Bp = (z < 7) ? (WA1 + z * 256 * 128) : (WB1 + (z - 7) * 256 * 128);
            bp = (z < 7) ? (bA1 + z * 128) : (bB1 + (z - 7) * 128);
            Cp = g_u1 + z * R1T * 128 + rt * 64 * 128;
        } else {
            int t2 = tile - 112; int z = t2 >> 6, rt = t2 & 63;
            Ap = g_x + R1T * 128 + rt * 64 * 128;
            Bp = ((z < 7) ? (WA1 + z * 256 * 128) : (WB1 + (z - 7) * 256 * 128)) + 128 * 128;
            Cp = g_u2 + z * R2T * 128 + rt * 64 * 128;
        }
        gemm64_tile(Ap, 128, Bp, 128, bp, Cp, 128, shA, shB);
    }
    grid_sync();

    // ================= F: pairwise energies =================
    {
        for (int i = t; i < 896; i += NTH) shB[i] = WA2[i];
        for (int i = t; i < 896; i += NTH) shB[896 + i] = WB2[i];
        float* sb2 = shA + 64;
        float* sC  = shA + 80;
        float* sBI = shA + 88;
        if (t < 7) {
            sb2[t] = bA2[t]; sC[t] = Cw[t];
            float bb = BCON[t];
            sBI[t] = 1.f / (3.f * bb * bb);
        } else if (t < 14) sb2[t] = bB2[t - 7];
        __syncthreads();
        int w = t >> 5;
        for (int it = 0; it < BB; it++) {
            int b = it, bx = blockIdx.x;
            if (t < 56) shA[t] = 0.f;   // part[8][7]
            __syncthreads();
            int pbase = bx * 128 + w * 16;
            for (int q = 0; q < 16; q++) {
                int pair = pbase + q;
                unsigned mask = g_mask[b * 32768 + pair];
                if (!mask) continue;
                int j = pair >> 9, k = pair & 511;
                int pidx = (b * NN1 + j) * NN2 + k;
                float d0 = dmv[pidx * 3 + 0];
                float d1 = dmv[pidx * 3 + 1];
                float d2 = dmv[pidx * 3 + 2];
                float dm = sqrtf(d0 * d0 + d1 * d1 + d2 * d2 + 1e-10f);
                if (dm < 0.5f) dm = 1e10f;
                while (mask) {
                    int i = __ffs(mask) - 1;
                    mask &= mask - 1;
                    float4 a1 = ((const float4*)(g_u1 + ((i * BB + b) * NN1 + j) * DD))[lane];
                    float4 a2 = ((const float4*)(g_u2 + ((i * BB + b) * NN2 + k) * DD))[lane];
                    float4 b1 = ((const float4*)(g_u1 + (((i + 7) * BB + b) * NN1 + j) * DD))[lane];
                    float4 b2 = ((const float4*)(g_u2 + (((i + 7) * BB + b) * NN2 + k) * DD))[lane];
                    float4 wa = *(const float4*)&shB[i * 128 + lane * 4];
                    float4 wb = *(const float4*)&shB[896 + i * 128 + lane * 4];
                    float sa = fmaxf(a1.x + a2.x, 0.f) * wa.x + fmaxf(a1.y + a2.y, 0.f) * wa.y
                             + fmaxf(a1.z + a2.z, 0.f) * wa.z + fmaxf(a1.w + a2.w, 0.f) * wa.w;
                    float sb = fmaxf(b1.x + b2.x, 0.f) * wb.x + fmaxf(b1.y + b2.y, 0.f) * wb.y
                             + fmaxf(b1.z + b2.z, 0.f) * wb.z + fmaxf(b1.w + b2.w, 0.f) * wb.w;
#pragma unroll
                    for (int o = 16; o; o >>= 1) {
                        sa += __shfl_xor_sync(0xffffffffu, sa, o);
                        sb += __shfl_xor_sync(0xffffffffu, sb, o);
                    }
                    if (lane == 0) {
                        float Aa = 4.f / (1.f + expf(-(sa + sb2[i])));
                        float bi = sBI[i];
                        float Bp2 = (2.f * bi) / (1.f + expf(-(sb + sb2[7 + i]))) + bi;
                        float dd = dm - sC[i];
                        shA[w * 7 + i] += Aa * (Bp2 * dd * dd - 1.f);
                    }
                }
            }
            __syncthreads();
            if (t < 7) {
                float s = 0.f;
#pragma unroll
                for (int q = 0; q < 8; q++) s += shA[q * 7 + t];
                g_partial[(b * NBLK + bx) * 7 + t] = s;
            }
            __syncthreads();
        }
    }
    grid_sync();

    // ================= G: reduce + intercept + output =================
    if (blockIdx.x < BB) {
        int b = blockIdx.x;
        float* red = shA;              // 256
        float* energy = shA + 272;     // 7
        float* pooled = shA + 288;     // 128
        float* svp = shA + 420;        // 1
        for (int i = 0; i < 7; i++) {
            red[t] = g_partial[(b * NBLK + t) * 7 + i];
            __syncthreads();
            for (int o = 128; o; o >>= 1) {
                if (t < o) red[t] += red[t + o];
                __syncthreads();
            }
            if (t == 0) energy[i] = red[0];
            __syncthreads();
        }
        if (t < 128) {
            float s = 0.f;
            for (int j = 0; j < NN1; j++)
                s += g_x[(b * NN1 + j) * 128 + t] * valid[b * NN1 + j];
            pooled[t] = s;
        }
        __syncthreads();
        if (t < 128) {
            float a = bi1[t];
            for (int d = 0; d < 128; d++) a += pooled[d] * Wi1[d * 128 + t];
            red[t] = fmaxf(a, 0.f) * Wi2[t];
        }
        __syncthreads();
        for (int o = 64; o; o >>= 1) {
            if (t < o) red[t] += red[t + o];
            __syncthreads();
        }
        if (t == 0) svp[0] = 4.f / (1.f + expf(-(red[0] + bi2[0])));
        __syncthreads();
        if (t < 7) out[b * 7 + t] = energy[t] + svp[0] / 7.f;
    }
}

// ---------------- host ----------------
extern "C" void kernel_launch(void* const* d_in, const int* in_sizes, int n_in,
                              void* d_out, int out_size)
{
    (void)in_sizes; (void)n_in; (void)out_size;
    mega<<<NBLK, NTH>>>(
        (const float*)d_in[0],  (const float*)d_in[1],  (const float*)d_in[2],
        (const float*)d_in[3],  (const float*)d_in[4],  (const float*)d_in[5],
        (const float*)d_in[6],  (const float*)d_in[7],  (const float*)d_in[8],
        (const float*)d_in[9],  (const float*)d_in[10], (const float*)d_in[11],
        (const float*)d_in[12], (const float*)d_in[13], (const float*)d_in[14],
        (const float*)d_in[15], (const float*)d_in[16], (const float*)d_in[17],
        (const float*)d_in[18], (const float*)d_in[19], (const float*)d_in[20],
        (const float*)d_in[21], (const float*)d_in[22], (const float*)d_in[23],
        (const float*)d_in[24], (const float*)d_in[25],
        (float*)d_out);
}

// round 5
// speedup vs baseline: 1.3610x; 1.3610x over previous
#include <cuda_runtime.h>
#include <math.h>

#define BB 8
#define NN1 64
#define NN2 512
#define DD 128
#define NL 3
#define NT 7
#define R1T (BB*NN1)            // 512
#define R2T (BB*NN2)            // 4096
#define RTOT (R1T+R2T)          // 4608
#define CAP 96
#define NBLKP 256

// ---------------- scratch ----------------
__device__ __align__(16) float g_x  [RTOT*DD];
__device__ __align__(16) float g_hc [RTOT*256];
__device__ __align__(16) float g_e1 [BB*NN1*NN1];
__device__ __align__(16) float g_e2 [BB*NN2*NN2];
__device__ __align__(16) float g_wc [NL*DD*256];
__device__ __align__(16) float g_bc [NL*256];
__device__ __align__(16) float g_u1 [14*R1T*DD];
__device__ __align__(16) float g_u2 [14*R2T*DD];
__device__ unsigned char g_maskb[BB*NN1*NN2];
__device__ float g_dm[BB*NN1*NN2];
__device__ float g_partial[BB*NBLKP*NT];
__device__ int   g_rl[RTOT*CAP];
__device__ int   g_rcnt[RTOT];
__device__ int   g_cl[RTOT*CAP];
__device__ int   g_ccnt[RTOT];

__constant__ float BCON[7] = {1.159f,0.448f,0.927f,0.902f,0.349f,0.789f,0.198f};

// ---------------- f32x2 helpers ----------------
__device__ __forceinline__ unsigned long long dup_f32(float x)
{
    unsigned long long d;
    asm("mov.b64 %0, {%1, %1};" : "=l"(d) : "f"(x));
    return d;
}
__device__ __forceinline__ void ffma2(unsigned long long& acc, unsigned long long a, unsigned long long b)
{
    asm("fma.rn.f32x2 %0, %1, %2, %0;" : "+l"(acc) : "l"(a), "l"(b));
}
__device__ __forceinline__ float2 unpk(unsigned long long v)
{
    float lo, hi;
    asm("mov.b64 {%0, %1}, %2;" : "=f"(lo), "=f"(hi) : "l"(v));
    return make_float2(lo, hi);
}

// ---------------- 32x128 tile GEMM (scalar, K guarded) ----------------
__device__ __forceinline__ void gemm32_tile(
    const float* __restrict__ A, int lda, int K,
    const float* __restrict__ B, int ldb,
    float* __restrict__ C, int ldc,
    float* As /*32*36*/, float* Bs /*32*128*/)
{
    int t = threadIdx.x, rq = t >> 5, cq = t & 31;
    float acc[4][4];
#pragma unroll
    for (int i = 0; i < 4; i++)
#pragma unroll
        for (int j = 0; j < 4; j++) acc[i][j] = 0.f;
    for (int k0 = 0; k0 < K; k0 += 32) {
#pragma unroll
        for (int s = 0; s < 4; s++) {
            int i = t + 256 * s, r = i >> 5, kk = i & 31, gk = k0 + kk;
            As[kk * 36 + r] = (gk < K) ? A[r * lda + gk] : 0.f;
        }
#pragma unroll
        for (int s = 0; s < 16; s++) {
            int i = t + 256 * s, kk = i >> 7, c = i & 127, gk = k0 + kk;
            Bs[kk * 128 + c] = (gk < K) ? B[gk * ldb + c] : 0.f;
        }
        __syncthreads();
#pragma unroll
        for (int kk = 0; kk < 32; kk++) {
            float4 av = *(const float4*)&As[kk * 36 + rq * 4];
            float4 bv = *(const float4*)&Bs[kk * 128 + cq * 4];
            float ar[4] = {av.x, av.y, av.z, av.w};
            float br[4] = {bv.x, bv.y, bv.z, bv.w};
#pragma unroll
            for (int i = 0; i < 4; i++)
#pragma unroll
                for (int j = 0; j < 4; j++) acc[i][j] += ar[i] * br[j];
        }
        __syncthreads();
    }
#pragma unroll
    for (int i = 0; i < 4; i++) {
        float4 o;
        o.x = acc[i][0]; o.y = acc[i][1]; o.z = acc[i][2]; o.w = acc[i][3];
        *(float4*)&C[(rq * 4 + i) * ldc + cq * 4] = o;
    }
}

// ---------------- 64x128 tile GEMM, K=128, FFMA2 inner ----------------
__device__ __forceinline__ void gemm64_tile(
    const float* __restrict__ A, int lda,
    const float* __restrict__ B, int ldb,
    const float* __restrict__ bias,
    float* __restrict__ C, int ldc,
    float* As /*32*68*/, float* Bs /*32*128*/)
{
    int t = threadIdx.x, w = t >> 5, lane = t & 31;
    unsigned long long acc2[4][4];   // [row-pair][col]
#pragma unroll
    for (int p = 0; p < 4; p++)
#pragma unroll
        for (int j = 0; j < 4; j++) acc2[p][j] = 0ull;
    for (int k0 = 0; k0 < 128; k0 += 32) {
#pragma unroll
        for (int s = 0; s < 8; s++) {
            int i = t + 256 * s, r = i >> 5, kk = i & 31;
            As[kk * 68 + r] = A[r * lda + k0 + kk];
        }
#pragma unroll
        for (int s = 0; s < 16; s++) {
            int i = t + 256 * s, kk = i >> 7, c = i & 127;
            Bs[kk * 128 + c] = B[(k0 + kk) * ldb + c];
        }
        __syncthreads();
#pragma unroll
        for (int kk = 0; kk < 32; kk++) {
            const ulonglong2* ap = (const ulonglong2*)&As[kk * 68 + w * 8];
            ulonglong2 a0 = ap[0], a1 = ap[1];
            unsigned long long ar[4] = {a0.x, a0.y, a1.x, a1.y};   // row pairs (0,1)(2,3)(4,5)(6,7)
            float4 bv = *(const float4*)&Bs[kk * 128 + lane * 4];
            unsigned long long br[4] = {dup_f32(bv.x), dup_f32(bv.y), dup_f32(bv.z), dup_f32(bv.w)};
#pragma unroll
            for (int p = 0; p < 4; p++)
#pragma unroll
                for (int j = 0; j < 4; j++) ffma2(acc2[p][j], ar[p], br[j]);
        }
        __syncthreads();
    }
    float4 bvv = make_float4(0.f, 0.f, 0.f, 0.f);
    if (bias) bvv = *(const float4*)&bias[lane * 4];
#pragma unroll
    for (int p = 0; p < 4; p++) {
        float2 v0 = unpk(acc2[p][0]), v1 = unpk(acc2[p][1]);
        float2 v2 = unpk(acc2[p][2]), v3 = unpk(acc2[p][3]);
        float4 olo, ohi;
        olo.x = v0.x + bvv.x; olo.y = v1.x + bvv.y; olo.z = v2.x + bvv.z; olo.w = v3.x + bvv.w;
        ohi.x = v0.y + bvv.x; ohi.y = v1.y + bvv.y; ohi.z = v2.y + bvv.z; ohi.w = v3.y + bvv.w;
        *(float4*)&C[(w * 8 + 2 * p) * ldc + lane * 4] = olo;
        *(float4*)&C[(w * 8 + 2 * p + 1) * ldc + lane * 4] = ohi;
    }
}

// ---------------- prep: weights || col-lists || row-lists || mask+dm || embed ----------------
#define PB_A 192
#define PB_B (PB_A + 18)
#define PB_C (PB_B + 576)
#define PB_D (PB_C + 1024)
#define PB_E (PB_D + 144)

__global__ void prep(const float* __restrict__ h1, const float* __restrict__ h2,
                     const float* __restrict__ adj1, const float* __restrict__ adj2,
                     const float* __restrict__ A_int, const float* __restrict__ dmv,
                     const float* __restrict__ W_embed,
                     const float* __restrict__ gW, const float* __restrict__ gA,
                     const float* __restrict__ gWb)
{
    __shared__ __align__(16) float shA[32 * 36];
    __shared__ __align__(16) float shB[32 * 128];
    int bx = blockIdx.x, t = threadIdx.x;

    if (bx < PB_A) {
        // combined GAT weights: Wc=[W | W@A], bc=[Wb | Wb@A]
        int idx = bx * 256 + t;
        int c = idx & 127, d = (idx >> 7) & 127, l = idx >> 14;
        const float* W = gW + l * DD * DD;
        const float* Am = gA + l * DD * DD;
        g_wc[(l * DD + d) * 256 + c] = W[d * DD + c];
        float s = 0.f;
#pragma unroll 8
        for (int dd = 0; dd < DD; dd++) s += W[d * DD + dd] * Am[dd * DD + c];
        g_wc[(l * DD + d) * 256 + 128 + c] = s;
        if (d == 0) {
            g_bc[l * 256 + c] = gWb[l * DD + c];
            float sb = 0.f;
#pragma unroll 8
            for (int dd = 0; dd < DD; dd++) sb += gWb[l * DD + dd] * Am[dd * DD + c];
            g_bc[l * 256 + 128 + c] = sb;
        }
    } else if (bx < PB_B) {
        // column adjacency lists: coladj[c] = { r : adj[r,c] != 0 }
        int cidx = (bx - PB_A) * 256 + t;
        const float* aj; int N, c;
        if (cidx < R1T) { int b = cidx >> 6; c = cidx & 63; N = NN1; aj = adj1 + b * NN1 * NN1; }
        else { int rr = cidx - R1T; int b = rr >> 9; c = rr & 511; N = NN2; aj = adj2 + b * NN2 * NN2; }
        int cnt = 0;
        for (int r = 0; r < N; r++) {
            if (aj[r * N + c] != 0.f) { if (cnt < CAP) g_cl[cidx * CAP + cnt] = r; cnt++; }
        }
        g_ccnt[cidx] = (cnt > CAP) ? CAP : cnt;
    } else if (bx < PB_C) {
        // row adjacency lists (coalesced ballot scan)
        int row = (bx - PB_B) * 8 + (t >> 5);
        int lane = t & 31;
        const float* aj; int N;
        if (row < R1T) { int b = row >> 6, r = row & 63; N = NN1; aj = adj1 + (b * NN1 + r) * NN1; }
        else { int rr = row - R1T; int b = rr >> 9, r = rr & 511; N = NN2; aj = adj2 + (b * NN2 + r) * NN2; }
        int cnt = 0;
        for (int base = 0; base < N; base += 32) {
            int c = base + lane;
            bool v = (aj[c] != 0.f);
            unsigned m = __ballot_sync(0xffffffffu, v);
            if (v) {
                int pos = cnt + __popc(m & ((1u << lane) - 1u));
                if (pos < CAP) g_rl[row * CAP + pos] = c;
            }
            cnt += __popc(m);
        }
        if (cnt > CAP) cnt = CAP;
        if (lane == 0) g_rcnt[row] = cnt;
    } else if (bx < PB_D) {
        // pack A_int into 7-bit mask + precompute dm, k-major layout
        int v = (bx - PB_C) * 256 + t;
        int k = v & 511, j = (v >> 9) & 63, b = v >> 15;
        unsigned m = 0;
#pragma unroll
        for (int i = 0; i < 7; i++)
            if (A_int[((b * 7 + i) * NN1 + j) * NN2 + k] != 0.f) m |= 1u << i;
        int po = b * 32768 + k * 64 + j;
        g_maskb[po] = (unsigned char)m;
        int pidx = (b * NN1 + j) * NN2 + k;
        float d0 = dmv[pidx * 3 + 0], d1 = dmv[pidx * 3 + 1], d2 = dmv[pidx * 3 + 2];
        float dm = sqrtf(d0 * d0 + d1 * d1 + d2 * d2 + 1e-10f);
        if (dm < 0.5f) dm = 1e10f;
        g_dm[po] = dm;
    } else {
        // embedding: x = h @ W_embed  (144 tiles of 32x128, K=56)
        int tile = bx - PB_D;
        int row0 = tile * 32;
        const float* Ap = (row0 < R1T) ? (h1 + row0 * 56) : (h2 + (row0 - R1T) * 56);
        gemm32_tile(Ap, 56, 56, W_embed, 128, g_x + row0 * 128, 128, shA, shB);
    }
}

// ---------------- layer GEMM: hc = x @ Wc + bc ----------------
__global__ void gemm_hc(const float* __restrict__ wc_l, const float* __restrict__ bc_l)
{
    __shared__ __align__(16) float shA[32 * 68];
    __shared__ __align__(16) float shB[32 * 128];
    int rowtile = blockIdx.x >> 1, colb = blockIdx.x & 1;
    gemm64_tile(g_x + rowtile * 64 * 128, 128,
                wc_l + colb * 128, 256,
                bc_l + colb * 128,
                g_hc + rowtile * 64 * 256 + colb * 128, 256, shA, shB);
}

// ---------------- column pass: e (register-buffered) -> normalized att ----------------
__global__ void stats_e()
{
    int cidx = blockIdx.x * 8 + (threadIdx.x >> 5);
    int lane = threadIdx.x & 31;
    int N, c, gbase; float* E;
    if (cidx < R1T) { int b = cidx >> 6; c = cidx & 63; N = NN1; gbase = b * NN1; E = g_e1 + b * NN1 * NN1; }
    else { int rr = cidx - R1T; int b = rr >> 9; c = rr & 511; N = NN2; gbase = R1T + b * NN2; E = g_e2 + b * NN2 * NN2; }

    float4 hcv  = *(const float4*)&g_hc[(gbase + c) * 256 + lane * 4];
    float4 hacv = *(const float4*)&g_hc[(gbase + c) * 256 + 128 + lane * 4];
    int cnt = g_ccnt[cidx];
    const int* cl = g_cl + cidx * CAP;

    float ebuf[3];
    float mx = -1e30f;
    for (int idx = 0; idx < cnt; idx++) {
        int r = cl[idx];
        int grow = gbase + r;
        float4 hr  = *(const float4*)&g_hc[grow * 256 + lane * 4];
        float4 har = *(const float4*)&g_hc[grow * 256 + 128 + lane * 4];
        float p = hacv.x * hr.x + hacv.y * hr.y + hacv.z * hr.z + hacv.w * hr.w
                + hcv.x * har.x + hcv.y * har.y + hcv.z * har.z + hcv.w * har.w;
#pragma unroll
        for (int o = 16; o; o >>= 1) p += __shfl_xor_sync(0xffffffffu, p, o);
        if ((idx & 31) == lane) ebuf[idx >> 5] = p;
        mx = fmaxf(mx, p);
    }
    float vbuf[3];
    float s = 0.f;
#pragma unroll
    for (int si = 0; si < 3; si++) {
        int idx = si * 32 + lane;
        if (idx < cnt) { vbuf[si] = expf(ebuf[si] - mx); s += vbuf[si]; }
    }
#pragma unroll
    for (int o = 16; o; o >>= 1) s += __shfl_xor_sync(0xffffffffu, s, o);
    float zi = 1.f / s;
#pragma unroll
    for (int si = 0; si < 3; si++) {
        int idx = si * 32 + lane;
        if (idx < cnt) E[cl[idx] * N + c] = vbuf[si] * zi;
    }
}

// ---------------- row pass: hp = relu(att @ h); x = cf*x + (1-cf)*hp ----------------
__global__ void att_gate(const float* __restrict__ Wg, const float* __restrict__ bg)
{
    int row = blockIdx.x * 8 + (threadIdx.x >> 5);
    int lane = threadIdx.x & 31;
    int N, r, gbase; const float* E;
    if (row < R1T) { int b = row >> 6; r = row & 63; N = NN1; gbase = b * NN1; E = g_e1 + b * NN1 * NN1; }
    else { int rr = row - R1T; int b = rr >> 9; r = rr & 511; N = NN2; gbase = R1T + b * NN2; E = g_e2 + b * NN2 * NN2; }

    float4 acc = make_float4(0.f, 0.f, 0.f, 0.f);
    int cnt = g_rcnt[row];
    const int* rl = g_rl + row * CAP;
    for (int idx = 0; idx < cnt; idx++) {
        int cc = rl[idx];
        float wv = E[r * N + cc];
        float4 hv = *(const float4*)&g_hc[(gbase + cc) * 256 + lane * 4];
        acc.x += wv * hv.x; acc.y += wv * hv.y; acc.z += wv * hv.z; acc.w += wv * hv.w;
    }
    float hp[4] = {fmaxf(acc.x, 0.f), fmaxf(acc.y, 0.f), fmaxf(acc.z, 0.f), fmaxf(acc.w, 0.f)};
    float4 xv4 = *(const float4*)&g_x[row * 128 + lane * 4];
    float xv[4] = {xv4.x, xv4.y, xv4.z, xv4.w};
    float4 wx4 = *(const float4*)&Wg[lane * 4];
    float4 wh4 = *(const float4*)&Wg[128 + lane * 4];
    float p = xv[0] * wx4.x + xv[1] * wx4.y + xv[2] * wx4.z + xv[3] * wx4.w
            + hp[0] * wh4.x + hp[1] * wh4.y + hp[2] * wh4.z + hp[3] * wh4.w;
#pragma unroll
    for (int o = 16; o; o >>= 1) p += __shfl_xor_sync(0xffffffffu, p, o);
    float cf = 1.f / (1.f + expf(-(p + bg[0])));
    float4 ov;
    ov.x = cf * xv[0] + (1.f - cf) * hp[0];
    ov.y = cf * xv[1] + (1.f - cf) * hp[1];
    ov.z = cf * xv[2] + (1.f - cf) * hp[2];
    ov.w = cf * xv[3] + (1.f - cf) * hp[3];
    *(float4*)&g_x[row * 128 + lane * 4] = ov;
}

// ---------------- u GEMMs: 1008 tiles of 64x128, K=128 ----------------
__global__ void u_gemms(const float* __restrict__ WA1, const float* __restrict__ bA1,
                        const float* __restrict__ WB1, const float* __restrict__ bB1)
{
    __shared__ __align__(16) float shA[32 * 68];
    __shared__ __align__(16) float shB[32 * 128];
    int tile = blockIdx.x;
    const float* Ap; const float* Bp; const float* bp = nullptr; float* Cp;
    if (tile < 112) {
        int z = tile >> 3, rt = tile & 7;
        Ap = g_x + rt * 64 * 128;
        Bp = (z < 7) ? (WA1 + z * 256 * 128) : (WB1 + (z - 7) * 256 * 128);
        bp = (z < 7) ? (bA1 + z * 128) : (bB1 + (z - 7) * 128);
        Cp = g_u1 + z * R1T * 128 + rt * 64 * 128;
    } else {
        int t2 = tile - 112; int z = t2 >> 6, rt = t2 & 63;
        Ap = g_x + R1T * 128 + rt * 64 * 128;
        Bp = ((z < 7) ? (WA1 + z * 256 * 128) : (WB1 + (z - 7) * 256 * 128)) + 128 * 128;
        Cp = g_u2 + z * R2T * 128 + rt * 64 * 128;
    }
    gemm64_tile(Ap, 128, Bp, 128, bp, Cp, 128, shA, shB);
}

// ---------------- pairwise energies (k-major, 16 pairs/warp) ----------------
__global__ void pair_energy(const float* __restrict__ WA2, const float* __restrict__ bA2,
                            const float* __restrict__ WB2, const float* __restrict__ bB2,
                            const float* __restrict__ Cc)
{
    __shared__ __align__(16) float sW[14][128];
    __shared__ float sb2[14], sC[7], sBI[7];
    __shared__ float part[8][7];
    int t = threadIdx.x;
    for (int i = t; i < 896; i += 256) sW[i >> 7][i & 127] = WA2[i];
    for (int i = t; i < 896; i += 256) sW[7 + (i >> 7)][i & 127] = WB2[i];
    if (t < 7) {
        sb2[t] = bA2[t]; sC[t] = Cc[t];
        float bb = BCON[t];
        sBI[t] = 1.f / (3.f * bb * bb);
    } else if (t < 14) sb2[t] = bB2[t - 7];
    if (t < 56) part[t / 7][t % 7] = 0.f;
    __syncthreads();

    int w = t >> 5, lane = t & 31;
    int b = blockIdx.y;
    int pbase = blockIdx.x * 128 + w * 16;        // p = k*64 + j

    for (int q = 0; q < 16; q++) {
        int p = pbase + q;
        unsigned mask = g_maskb[b * 32768 + p];
        if (!mask) continue;
        int j = p & 63, k = p >> 6;
        float dm = g_dm[b * 32768 + p];
        while (mask) {
            int i = __ffs(mask) - 1;
            mask &= mask - 1;
            float4 a1 = ((const float4*)(g_u1 + ((i * BB + b) * NN1 + j) * DD))[lane];
            float4 a2 = ((const float4*)(g_u2 + ((i * BB + b) * NN2 + k) * DD))[lane];
            float4 b1 = ((const float4*)(g_u1 + (((i + 7) * BB + b) * NN1 + j) * DD))[lane];
            float4 b2 = ((const float4*)(g_u2 + (((i + 7) * BB + b) * NN2 + k) * DD))[lane];
            float4 wa = *(const float4*)&sW[i][lane * 4];
            float4 wb = *(const float4*)&sW[7 + i][lane * 4];
            float sa = fmaxf(a1.x + a2.x, 0.f) * wa.x + fmaxf(a1.y + a2.y, 0.f) * wa.y
                     + fmaxf(a1.z + a2.z, 0.f) * wa.z + fmaxf(a1.w + a2.w, 0.f) * wa.w;
            float sb = fmaxf(b1.x + b2.x, 0.f) * wb.x + fmaxf(b1.y + b2.y, 0.f) * wb.y
                     + fmaxf(b1.z + b2.z, 0.f) * wb.z + fmaxf(b1.w + b2.w, 0.f) * wb.w;
#pragma unroll
            for (int o = 16; o; o >>= 1) {
                sa += __shfl_xor_sync(0xffffffffu, sa, o);
                sb += __shfl_xor_sync(0xffffffffu, sb, o);
            }
            if (lane == 0) {
                float Aa = 4.f / (1.f + expf(-(sa + sb2[i])));
                float bi = sBI[i];
                float Bp2 = (2.f * bi) / (1.f + expf(-(sb + sb2[7 + i]))) + bi;
                float dd = dm - sC[i];
                part[w][i] += Aa * (Bp2 * dd * dd - 1.f);
            }
        }
    }
    __syncthreads();
    if (t < 7) {
        float s = 0.f;
#pragma unroll
        for (int q = 0; q < 8; q++) s += part[q][t];
        g_partial[(b * NBLKP + blockIdx.x) * 7 + t] = s;
    }
}

// ---------------- energy reduce + intercept + output ----------------
__global__ void final_k(const float* __restrict__ valid,
                        const float* __restrict__ Wi1, const float* __restrict__ bi1,
                        const float* __restrict__ Wi2, const float* __restrict__ bi2,
                        float* __restrict__ out)
{
    int b = blockIdx.x, t = threadIdx.x;   // 128 threads
    __shared__ float red[128], energy[7], pooled[128], sv;
    for (int i = 0; i < 7; i++) {
        red[t] = g_partial[(b * NBLKP + t) * 7 + i]
               + g_partial[(b * NBLKP + t + 128) * 7 + i];
        __syncthreads();
        for (int o = 64; o; o >>= 1) {
            if (t < o) red[t] += red[t + o];
            __syncthreads();
        }
        if (t == 0) energy[i] = red[0];
        __syncthreads();
    }
    float s = 0.f;
    for (int j = 0; j < NN1; j++)
        s += g_x[(b * NN1 + j) * DD + t] * valid[b * NN1 + j];
    pooled[t] = s;
    __syncthreads();
    float a = bi1[t];
    for (int d = 0; d < 128; d++) a += pooled[d] * Wi1[d * 128 + t];
    red[t] = fmaxf(a, 0.f) * Wi2[t];
    __syncthreads();
    for (int o = 64; o; o >>= 1) {
        if (t < o) red[t] += red[t + o];
        __syncthreads();
    }
    if (t == 0) sv = 4.f / (1.f + expf(-(red[0] + bi2[0])));
    __syncthreads();
    if (t < 7) out[b * 7 + t] = energy[t] + sv / 7.f;
}

// ---------------- host ----------------
static inline float* symaddr(const void* sym)
{
    void* p = nullptr;
    cudaGetSymbolAddress(&p, sym);
    return (float*)p;
}

extern "C" void kernel_launch(void* const* d_in, const int* in_sizes, int n_in,
                              void* d_out, int out_size)
{
    (void)in_sizes; (void)n_in; (void)out_size;
    const float* h1      = (const float*)d_in[0];
    const float* adj1    = (const float*)d_in[1];
    const float* h2      = (const float*)d_in[2];
    const float* adj2    = (const float*)d_in[3];
    const float* A_int   = (const float*)d_in[4];
    const float* dmv     = (const float*)d_in[5];
    const float* valid   = (const float*)d_in[6];
    const float* W_embed = (const float*)d_in[7];
    const float* gW      = (const float*)d_in[8];
    const float* gWb     = (const float*)d_in[9];
    const float* gA      = (const float*)d_in[10];
    const float* gGateW  = (const float*)d_in[11];
    const float* gGateb  = (const float*)d_in[12];
    const float* WA1     = (const float*)d_in[13];
    const float* bA1     = (const float*)d_in[14];
    const float* WA2     = (const float*)d_in[15];
    const float* bA2     = (const float*)d_in[16];
    const float* WB1     = (const float*)d_in[17];
    const float* bB1     = (const float*)d_in[18];
    const float* WB2     = (const float*)d_in[19];
    const float* bB2     = (const float*)d_in[20];
    const float* Cw      = (const float*)d_in[21];
    const float* Wi1     = (const float*)d_in[22];
    const float* bi1     = (const float*)d_in[23];
    const float* Wi2     = (const float*)d_in[24];
    const float* bi2     = (const float*)d_in[25];
    float* out = (float*)d_out;

    float* p_wc = symaddr(g_wc);
    float* p_bc = symaddr(g_bc);

    prep<<<PB_E, 256>>>(h1, h2, adj1, adj2, A_int, dmv, W_embed, gW, gA, gWb);

    for (int l = 0; l < NL; l++) {
        gemm_hc<<<144, 256>>>(p_wc + l * DD * 256, p_bc + l * 256);
        stats_e<<<576, 256>>>();
        att_gate<<<576, 256>>>(gGateW + l * 256, gGateb + l);
    }

    u_gemms<<<1008, 256>>>(WA1, bA1, WB1, bB1);
    pair_energy<<<dim3(NBLKP, BB), 256>>>(WA2, bA2, WB2, bB2, Cw);
    final_k<<<BB, 128>>>(valid, Wi1, bi1, Wi2, bi2, out);
}

// round 6
// speedup vs baseline: 1.3987x; 1.0277x over previous
#include <cuda_runtime.h>
#include <math.h>

#define BB 8
#define NN1 64
#define NN2 512
#define DD 128
#define NL 3
#define NT 7
#define R1T (BB*NN1)            // 512
#define R2T (BB*NN2)            // 4096
#define RTOT (R1T+R2T)          // 4608
#define CAP 96
#define NBLKP 256

// ---------------- scratch ----------------
__device__ __align__(16) float g_x  [RTOT*DD];
__device__ __align__(16) float g_hc [RTOT*256];
__device__ __align__(16) float g_e1 [BB*NN1*NN1];
__device__ __align__(16) float g_e2 [BB*NN2*NN2];
__device__ __align__(16) float g_wc [NL*DD*256];
__device__ __align__(16) float g_bc [NL*256];
__device__ __align__(16) float g_u1 [14*R1T*DD];
__device__ __align__(16) float g_u2 [14*R2T*DD];
__device__ unsigned char g_maskb[BB*NN1*NN2];
__device__ float g_dm[BB*NN1*NN2];
__device__ float g_partial[BB*NBLKP*NT];
__device__ int   g_rl[RTOT*CAP];
__device__ int   g_rcnt[RTOT];
__device__ int   g_cl[RTOT*CAP];
__device__ int   g_ccnt[RTOT];

__constant__ float BCON[7] = {1.159f,0.448f,0.927f,0.902f,0.349f,0.789f,0.198f};

// ---------------- f32x2 helpers ----------------
__device__ __forceinline__ unsigned long long dup_f32(float x)
{
    unsigned long long d;
    asm("mov.b64 %0, {%1, %1};" : "=l"(d) : "f"(x));
    return d;
}
__device__ __forceinline__ void ffma2(unsigned long long& acc, unsigned long long a, unsigned long long b)
{
    asm("fma.rn.f32x2 %0, %1, %2, %0;" : "+l"(acc) : "l"(a), "l"(b));
}
__device__ __forceinline__ float2 unpk(unsigned long long v)
{
    float lo, hi;
    asm("mov.b64 {%0, %1}, %2;" : "=f"(lo), "=f"(hi) : "l"(v));
    return make_float2(lo, hi);
}

// ---------------- 32x128 tile GEMM (scalar, K guarded) ----------------
__device__ __forceinline__ void gemm32_tile(
    const float* __restrict__ A, int lda, int K,
    const float* __restrict__ B, int ldb,
    float* __restrict__ C, int ldc,
    float* As /*32*36*/, float* Bs /*32*128*/)
{
    int t = threadIdx.x, rq = t >> 5, cq = t & 31;
    float acc[4][4];
#pragma unroll
    for (int i = 0; i < 4; i++)
#pragma unroll
        for (int j = 0; j < 4; j++) acc[i][j] = 0.f;
    for (int k0 = 0; k0 < K; k0 += 32) {
#pragma unroll
        for (int s = 0; s < 4; s++) {
            int i = t + 256 * s, r = i >> 5, kk = i & 31, gk = k0 + kk;
            As[kk * 36 + r] = (gk < K) ? A[r * lda + gk] : 0.f;
        }
#pragma unroll
        for (int s = 0; s < 16; s++) {
            int i = t + 256 * s, kk = i >> 7, c = i & 127, gk = k0 + kk;
            Bs[kk * 128 + c] = (gk < K) ? B[gk * ldb + c] : 0.f;
        }
        __syncthreads();
#pragma unroll
        for (int kk = 0; kk < 32; kk++) {
            float4 av = *(const float4*)&As[kk * 36 + rq * 4];
            float4 bv = *(const float4*)&Bs[kk * 128 + cq * 4];
            float ar[4] = {av.x, av.y, av.z, av.w};
            float br[4] = {bv.x, bv.y, bv.z, bv.w};
#pragma unroll
            for (int i = 0; i < 4; i++)
#pragma unroll
                for (int j = 0; j < 4; j++) acc[i][j] += ar[i] * br[j];
        }
        __syncthreads();
    }
#pragma unroll
    for (int i = 0; i < 4; i++) {
        float4 o;
        o.x = acc[i][0]; o.y = acc[i][1]; o.z = acc[i][2]; o.w = acc[i][3];
        *(float4*)&C[(rq * 4 + i) * ldc + cq * 4] = o;
    }
}

// ---------------- 64x128 tile GEMM, K=128, FFMA2 inner ----------------
__device__ __forceinline__ void gemm64_tile(
    const float* __restrict__ A, int lda,
    const float* __restrict__ B, int ldb,
    const float* __restrict__ bias,
    float* __restrict__ C, int ldc,
    float* As /*32*68*/, float* Bs /*32*128*/)
{
    int t = threadIdx.x, w = t >> 5, lane = t & 31;
    unsigned long long acc2[4][4];   // [row-pair][col]
#pragma unroll
    for (int p = 0; p < 4; p++)
#pragma unroll
        for (int j = 0; j < 4; j++) acc2[p][j] = 0ull;
    for (int k0 = 0; k0 < 128; k0 += 32) {
#pragma unroll
        for (int s = 0; s < 8; s++) {
            int i = t + 256 * s, r = i >> 5, kk = i & 31;
            As[kk * 68 + r] = A[r * lda + k0 + kk];
        }
#pragma unroll
        for (int s = 0; s < 16; s++) {
            int i = t + 256 * s, kk = i >> 7, c = i & 127;
            Bs[kk * 128 + c] = B[(k0 + kk) * ldb + c];
        }
        __syncthreads();
#pragma unroll
        for (int kk = 0; kk < 32; kk++) {
            const ulonglong2* ap = (const ulonglong2*)&As[kk * 68 + w * 8];
            ulonglong2 a0 = ap[0], a1 = ap[1];
            unsigned long long ar[4] = {a0.x, a0.y, a1.x, a1.y};
            float4 bv = *(const float4*)&Bs[kk * 128 + lane * 4];
            unsigned long long br[4] = {dup_f32(bv.x), dup_f32(bv.y), dup_f32(bv.z), dup_f32(bv.w)};
#pragma unroll
            for (int p = 0; p < 4; p++)
#pragma unroll
                for (int j = 0; j < 4; j++) ffma2(acc2[p][j], ar[p], br[j]);
        }
        __syncthreads();
    }
    float4 bvv = make_float4(0.f, 0.f, 0.f, 0.f);
    if (bias) bvv = *(const float4*)&bias[lane * 4];
#pragma unroll
    for (int p = 0; p < 4; p++) {
        float2 v0 = unpk(acc2[p][0]), v1 = unpk(acc2[p][1]);
        float2 v2 = unpk(acc2[p][2]), v3 = unpk(acc2[p][3]);
        float4 olo, ohi;
        olo.x = v0.x + bvv.x; olo.y = v1.x + bvv.y; olo.z = v2.x + bvv.z; olo.w = v3.x + bvv.w;
        ohi.x = v0.y + bvv.x; ohi.y = v1.y + bvv.y; ohi.z = v2.y + bvv.z; ohi.w = v3.y + bvv.w;
        *(float4*)&C[(w * 8 + 2 * p) * ldc + lane * 4] = olo;
        *(float4*)&C[(w * 8 + 2 * p + 1) * ldc + lane * 4] = ohi;
    }
}

// ---------------- prep: weights || col-lists || row-lists || mask+dm || embed ----------------
#define PB_A 192
#define PB_B (PB_A + 18)
#define PB_C (PB_B + 576)
#define PB_D (PB_C + 1024)
#define PB_E (PB_D + 144)

__global__ void prep(const float* __restrict__ h1, const float* __restrict__ h2,
                     const float* __restrict__ adj1, const float* __restrict__ adj2,
                     const float* __restrict__ A_int, const float* __restrict__ dmv,
                     const float* __restrict__ W_embed,
                     const float* __restrict__ gW, const float* __restrict__ gA,
                     const float* __restrict__ gWb)
{
    __shared__ __align__(16) float shA[32 * 36];
    __shared__ __align__(16) float shB[32 * 128];
    int bx = blockIdx.x, t = threadIdx.x;

    if (bx < PB_A) {
        int idx = bx * 256 + t;
        int c = idx & 127, d = (idx >> 7) & 127, l = idx >> 14;
        const float* W = gW + l * DD * DD;
        const float* Am = gA + l * DD * DD;
        g_wc[(l * DD + d) * 256 + c] = W[d * DD + c];
        float s = 0.f;
#pragma unroll 8
        for (int dd = 0; dd < DD; dd++) s += W[d * DD + dd] * Am[dd * DD + c];
        g_wc[(l * DD + d) * 256 + 128 + c] = s;
        if (d == 0) {
            g_bc[l * 256 + c] = gWb[l * DD + c];
            float sb = 0.f;
#pragma unroll 8
            for (int dd = 0; dd < DD; dd++) sb += gWb[l * DD + dd] * Am[dd * DD + c];
            g_bc[l * 256 + 128 + c] = sb;
        }
    } else if (bx < PB_B) {
        int cidx = (bx - PB_A) * 256 + t;
        const float* aj; int N, c;
        if (cidx < R1T) { int b = cidx >> 6; c = cidx & 63; N = NN1; aj = adj1 + b * NN1 * NN1; }
        else { int rr = cidx - R1T; int b = rr >> 9; c = rr & 511; N = NN2; aj = adj2 + b * NN2 * NN2; }
        int cnt = 0;
        for (int r = 0; r < N; r++) {
            if (aj[r * N + c] != 0.f) { if (cnt < CAP) g_cl[cidx * CAP + cnt] = r; cnt++; }
        }
        g_ccnt[cidx] = (cnt > CAP) ? CAP : cnt;
    } else if (bx < PB_C) {
        int row = (bx - PB_B) * 8 + (t >> 5);
        int lane = t & 31;
        const float* aj; int N;
        if (row < R1T) { int b = row >> 6, r = row & 63; N = NN1; aj = adj1 + (b * NN1 + r) * NN1; }
        else { int rr = row - R1T; int b = rr >> 9, r = rr & 511; N = NN2; aj = adj2 + (b * NN2 + r) * NN2; }
        int cnt = 0;
        for (int base = 0; base < N; base += 32) {
            int c = base + lane;
            bool v = (aj[c] != 0.f);
            unsigned m = __ballot_sync(0xffffffffu, v);
            if (v) {
                int pos = cnt + __popc(m & ((1u << lane) - 1u));
                if (pos < CAP) g_rl[row * CAP + pos] = c;
            }
            cnt += __popc(m);
        }
        if (cnt > CAP) cnt = CAP;
        if (lane == 0) g_rcnt[row] = cnt;
    } else if (bx < PB_D) {
        int v = (bx - PB_C) * 256 + t;
        int k = v & 511, j = (v >> 9) & 63, b = v >> 15;
        unsigned m = 0;
#pragma unroll
        for (int i = 0; i < 7; i++)
            if (A_int[((b * 7 + i) * NN1 + j) * NN2 + k] != 0.f) m |= 1u << i;
        int po = b * 32768 + k * 64 + j;
        g_maskb[po] = (unsigned char)m;
        int pidx = (b * NN1 + j) * NN2 + k;
        float d0 = dmv[pidx * 3 + 0], d1 = dmv[pidx * 3 + 1], d2 = dmv[pidx * 3 + 2];
        float dm = sqrtf(d0 * d0 + d1 * d1 + d2 * d2 + 1e-10f);
        if (dm < 0.5f) dm = 1e10f;
        g_dm[po] = dm;
    } else {
        int tile = bx - PB_D;
        int row0 = tile * 32;
        const float* Ap = (row0 < R1T) ? (h1 + row0 * 56) : (h2 + (row0 - R1T) * 56);
        gemm32_tile(Ap, 56, 56, W_embed, 128, g_x + row0 * 128, 128, shA, shB);
    }
}

// ---------------- layer GEMM: hc = x @ Wc + bc ----------------
__global__ void gemm_hc(const float* __restrict__ wc_l, const float* __restrict__ bc_l)
{
    __shared__ __align__(16) float shA[32 * 68];
    __shared__ __align__(16) float shB[32 * 128];
    int rowtile = blockIdx.x >> 1, colb = blockIdx.x & 1;
    gemm64_tile(g_x + rowtile * 64 * 128, 128,
                wc_l + colb * 128, 256,
                bc_l + colb * 128,
                g_hc + rowtile * 64 * 256 + colb * 128, 256, shA, shB);
}

// ---------------- column pass: e -> normalized att (unroll-4, interleaved reduces) ----------------
__global__ void stats_e()
{
    int cidx = blockIdx.x * 8 + (threadIdx.x >> 5);
    int lane = threadIdx.x & 31;
    int N, c, gbase; float* E;
    if (cidx < R1T) { int b = cidx >> 6; c = cidx & 63; N = NN1; gbase = b * NN1; E = g_e1 + b * NN1 * NN1; }
    else { int rr = cidx - R1T; int b = rr >> 9; c = rr & 511; N = NN2; gbase = R1T + b * NN2; E = g_e2 + b * NN2 * NN2; }

    float4 hcv  = *(const float4*)&g_hc[(gbase + c) * 256 + lane * 4];
    float4 hacv = *(const float4*)&g_hc[(gbase + c) * 256 + 128 + lane * 4];
    int cnt = g_ccnt[cidx];
    const int* cl = g_cl + cidx * CAP;

    float ebuf[3];
    float mx = -1e30f;
    int idx = 0;
    for (; idx + 4 <= cnt; idx += 4) {
        int r0 = cl[idx], r1 = cl[idx + 1], r2 = cl[idx + 2], r3 = cl[idx + 3];
        const float* p0 = &g_hc[(gbase + r0) * 256 + lane * 4];
        const float* p1 = &g_hc[(gbase + r1) * 256 + lane * 4];
        const float* p2 = &g_hc[(gbase + r2) * 256 + lane * 4];
        const float* p3 = &g_hc[(gbase + r3) * 256 + lane * 4];
        float4 h0 = *(const float4*)p0, ha0 = *(const float4*)(p0 + 128);
        float4 h1 = *(const float4*)p1, ha1 = *(const float4*)(p1 + 128);
        float4 h2 = *(const float4*)p2, ha2 = *(const float4*)(p2 + 128);
        float4 h3 = *(const float4*)p3, ha3 = *(const float4*)(p3 + 128);
        float e0 = hacv.x * h0.x + hacv.y * h0.y + hacv.z * h0.z + hacv.w * h0.w
                 + hcv.x * ha0.x + hcv.y * ha0.y + hcv.z * ha0.z + hcv.w * ha0.w;
        float e1 = hacv.x * h1.x + hacv.y * h1.y + hacv.z * h1.z + hacv.w * h1.w
                 + hcv.x * ha1.x + hcv.y * ha1.y + hcv.z * ha1.z + hcv.w * ha1.w;
        float e2 = hacv.x * h2.x + hacv.y * h2.y + hacv.z * h2.z + hacv.w * h2.w
                 + hcv.x * ha2.x + hcv.y * ha2.y + hcv.z * ha2.z + hcv.w * ha2.w;
        float e3 = hacv.x * h3.x + hacv.y * h3.y + hacv.z * h3.z + hacv.w * h3.w
                 + hcv.x * ha3.x + hcv.y * ha3.y + hcv.z * ha3.z + hcv.w * ha3.w;
#pragma unroll
        for (int o = 16; o; o >>= 1) {
            e0 += __shfl_xor_sync(0xffffffffu, e0, o);
            e1 += __shfl_xor_sync(0xffffffffu, e1, o);
            e2 += __shfl_xor_sync(0xffffffffu, e2, o);
            e3 += __shfl_xor_sync(0xffffffffu, e3, o);
        }
        if (lane == ((idx + 0) & 31)) ebuf[(idx + 0) >> 5] = e0;
        if (lane == ((idx + 1) & 31)) ebuf[(idx + 1) >> 5] = e1;
        if (lane == ((idx + 2) & 31)) ebuf[(idx + 2) >> 5] = e2;
        if (lane == ((idx + 3) & 31)) ebuf[(idx + 3) >> 5] = e3;
        mx = fmaxf(mx, fmaxf(fmaxf(e0, e1), fmaxf(e2, e3)));
    }
    for (; idx < cnt; idx++) {
        int r = cl[idx];
        const float* pr = &g_hc[(gbase + r) * 256 + lane * 4];
        float4 hr = *(const float4*)pr, har = *(const float4*)(pr + 128);
        float p = hacv.x * hr.x + hacv.y * hr.y + hacv.z * hr.z + hacv.w * hr.w
                + hcv.x * har.x + hcv.y * har.y + hcv.z * har.z + hcv.w * har.w;
#pragma unroll
        for (int o = 16; o; o >>= 1) p += __shfl_xor_sync(0xffffffffu, p, o);
        if (lane == (idx & 31)) ebuf[idx >> 5] = p;
        mx = fmaxf(mx, p);
    }
    float vbuf[3];
    float s = 0.f;
#pragma unroll
    for (int si = 0; si < 3; si++) {
        int ii = si * 32 + lane;
        if (ii < cnt) { vbuf[si] = expf(ebuf[si] - mx); s += vbuf[si]; }
    }
#pragma unroll
    for (int o = 16; o; o >>= 1) s += __shfl_xor_sync(0xffffffffu, s, o);
    float zi = 1.f / s;
#pragma unroll
    for (int si = 0; si < 3; si++) {
        int ii = si * 32 + lane;
        if (ii < cnt) E[cl[ii] * N + c] = vbuf[si] * zi;
    }
}

// ---------------- row pass: hp = relu(att@h); gate (unroll-4, 4 accumulators) ----------------
__global__ void att_gate(const float* __restrict__ Wg, const float* __restrict__ bg)
{
    int row = blockIdx.x * 8 + (threadIdx.x >> 5);
    int lane = threadIdx.x & 31;
    int N, r, gbase; const float* E;
    if (row < R1T) { int b = row >> 6; r = row & 63; N = NN1; gbase = b * NN1; E = g_e1 + b * NN1 * NN1; }
    else { int rr = row - R1T; int b = rr >> 9; r = rr & 511; N = NN2; gbase = R1T + b * NN2; E = g_e2 + b * NN2 * NN2; }

    float4 acc0 = make_float4(0.f, 0.f, 0.f, 0.f);
    float4 acc1 = make_float4(0.f, 0.f, 0.f, 0.f);
    float4 acc2 = make_float4(0.f, 0.f, 0.f, 0.f);
    float4 acc3 = make_float4(0.f, 0.f, 0.f, 0.f);
    int cnt = g_rcnt[row];
    const int* rl = g_rl + row * CAP;
    const float* Er = E + r * N;
    int idx = 0;
    for (; idx + 4 <= cnt; idx += 4) {
        int c0 = rl[idx], c1 = rl[idx + 1], c2 = rl[idx + 2], c3 = rl[idx + 3];
        float w0 = Er[c0], w1 = Er[c1], w2 = Er[c2], w3 = Er[c3];
        float4 h0 = *(const float4*)&g_hc[(gbase + c0) * 256 + lane * 4];
        float4 h1 = *(const float4*)&g_hc[(gbase + c1) * 256 + lane * 4];
        float4 h2 = *(const float4*)&g_hc[(gbase + c2) * 256 + lane * 4];
        float4 h3 = *(const float4*)&g_hc[(gbase + c3) * 256 + lane * 4];
        acc0.x += w0 * h0.x; acc0.y += w0 * h0.y; acc0.z += w0 * h0.z; acc0.w += w0 * h0.w;
        acc1.x += w1 * h1.x; acc1.y += w1 * h1.y; acc1.z += w1 * h1.z; acc1.w += w1 * h1.w;
        acc2.x += w2 * h2.x; acc2.y += w2 * h2.y; acc2.z += w2 * h2.z; acc2.w += w2 * h2.w;
        acc3.x += w3 * h3.x; acc3.y += w3 * h3.y; acc3.z += w3 * h3.z; acc3.w += w3 * h3.w;
    }
    for (; idx < cnt; idx++) {
        int cc = rl[idx];
        float wv = Er[cc];
        float4 hv = *(const float4*)&g_hc[(gbase + cc) * 256 + lane * 4];
        acc0.x += wv * hv.x; acc0.y += wv * hv.y; acc0.z += wv * hv.z; acc0.w += wv * hv.w;
    }
    float4 acc;
    acc.x = (acc0.x + acc1.x) + (acc2.x + acc3.x);
    acc.y = (acc0.y + acc1.y) + (acc2.y + acc3.y);
    acc.z = (acc0.z + acc1.z) + (acc2.z + acc3.z);
    acc.w = (acc0.w + acc1.w) + (acc2.w + acc3.w);
    float hp[4] = {fmaxf(acc.x, 0.f), fmaxf(acc.y, 0.f), fmaxf(acc.z, 0.f), fmaxf(acc.w, 0.f)};
    float4 xv4 = *(const float4*)&g_x[row * 128 + lane * 4];
    float xv[4] = {xv4.x, xv4.y, xv4.z, xv4.w};
    float4 wx4 = *(const float4*)&Wg[lane * 4];
    float4 wh4 = *(const float4*)&Wg[128 + lane * 4];
    float p = xv[0] * wx4.x + xv[1] * wx4.y + xv[2] * wx4.z + xv[3] * wx4.w
            + hp[0] * wh4.x + hp[1] * wh4.y + hp[2] * wh4.z + hp[3] * wh4.w;
#pragma unroll
    for (int o = 16; o; o >>= 1) p += __shfl_xor_sync(0xffffffffu, p, o);
    float cf = 1.f / (1.f + expf(-(p + bg[0])));
    float4 ov;
    ov.x = cf * xv[0] + (1.f - cf) * hp[0];
    ov.y = cf * xv[1] + (1.f - cf) * hp[1];
    ov.z = cf * xv[2] + (1.f - cf) * hp[2];
    ov.w = cf * xv[3] + (1.f - cf) * hp[3];
    *(float4*)&g_x[row * 128 + lane * 4] = ov;
}

// ---------------- u GEMMs: 1008 tiles of 64x128, K=128 ----------------
__global__ void u_gemms(const float* __restrict__ WA1, const float* __restrict__ bA1,
                        const float* __restrict__ WB1, const float* __restrict__ bB1)
{
    __shared__ __align__(16) float shA[32 * 68];
    __shared__ __align__(16) float shB[32 * 128];
    int tile = blockIdx.x;
    const float* Ap; const float* Bp; const float* bp = nullptr; float* Cp;
    if (tile < 112) {
        int z = tile >> 3, rt = tile & 7;
        Ap = g_x + rt * 64 * 128;
        Bp = (z < 7) ? (WA1 + z * 256 * 128) : (WB1 + (z - 7) * 256 * 128);
        bp = (z < 7) ? (bA1 + z * 128) : (bB1 + (z - 7) * 128);
        Cp = g_u1 + z * R1T * 128 + rt * 64 * 128;
    } else {
        int t2 = tile - 112; int z = t2 >> 6, rt = t2 & 63;
        Ap = g_x + R1T * 128 + rt * 64 * 128;
        Bp = ((z < 7) ? (WA1 + z * 256 * 128) : (WB1 + (z - 7) * 256 * 128)) + 128 * 128;
        Cp = g_u2 + z * R2T * 128 + rt * 64 * 128;
    }
    gemm64_tile(Ap, 128, Bp, 128, bp, Cp, 128, shA, shB);
}

// ---------------- pairwise energies (k-major, 16 pairs/warp) ----------------
__global__ void pair_energy(const float* __restrict__ WA2, const float* __restrict__ bA2,
                            const float* __restrict__ WB2, const float* __restrict__ bB2,
                            const float* __restrict__ Cc)
{
    __shared__ __align__(16) float sW[14][128];
    __shared__ float sb2[14], sC[7], sBI[7];
    __shared__ float part[8][7];
    int t = threadIdx.x;
    for (int i = t; i < 896; i += 256) sW[i >> 7][i & 127] = WA2[i];
    for (int i = t; i < 896; i += 256) sW[7 + (i >> 7)][i & 127] = WB2[i];
    if (t < 7) {
        sb2[t] = bA2[t]; sC[t] = Cc[t];
        float bb = BCON[t];
        sBI[t] = 1.f / (3.f * bb * bb);
    } else if (t < 14) sb2[t] = bB2[t - 7];
    if (t < 56) part[t / 7][t % 7] = 0.f;
    __syncthreads();

    int w = t >> 5, lane = t & 31;
    int b = blockIdx.y;
    int pbase = blockIdx.x * 128 + w * 16;        // p = k*64 + j

    for (int q = 0; q < 16; q++) {
        int p = pbase + q;
        unsigned mask = g_maskb[b * 32768 + p];
        if (!mask) continue;
        int j = p & 63, k = p >> 6;
        float dm = g_dm[b * 32768 + p];
        while (mask) {
            int i = __ffs(mask) - 1;
            mask &= mask - 1;
            float4 a1 = ((const float4*)(g_u1 + ((i * BB + b) * NN1 + j) * DD))[lane];
            float4 a2 = ((const float4*)(g_u2 + ((i * BB + b) * NN2 + k) * DD))[lane];
            float4 b1 = ((const float4*)(g_u1 + (((i + 7) * BB + b) * NN1 + j) * DD))[lane];
            float4 b2 = ((const float4*)(g_u2 + (((i + 7) * BB + b) * NN2 + k) * DD))[lane];
            float4 wa = *(const float4*)&sW[i][lane * 4];
            float4 wb = *(const float4*)&sW[7 + i][lane * 4];
            float sa = fmaxf(a1.x + a2.x, 0.f) * wa.x + fmaxf(a1.y + a2.y, 0.f) * wa.y
                     + fmaxf(a1.z + a2.z, 0.f) * wa.z + fmaxf(a1.w + a2.w, 0.f) * wa.w;
            float sb = fmaxf(b1.x + b2.x, 0.f) * wb.x + fmaxf(b1.y + b2.y, 0.f) * wb.y
                     + fmaxf(b1.z + b2.z, 0.f) * wb.z + fmaxf(b1.w + b2.w, 0.f) * wb.w;
#pragma unroll
            for (int o = 16; o; o >>= 1) {
                sa += __shfl_xor_sync(0xffffffffu, sa, o);
                sb += __shfl_xor_sync(0xffffffffu, sb, o);
            }
            if (lane == 0) {
                float Aa = 4.f / (1.f + expf(-(sa + sb2[i])));
                float bi = sBI[i];
                float Bp2 = (2.f * bi) / (1.f + expf(-(sb + sb2[7 + i]))) + bi;
                float dd = dm - sC[i];
                part[w][i] += Aa * (Bp2 * dd * dd - 1.f);
            }
        }
    }
    __syncthreads();
    if (t < 7) {
        float s = 0.f;
#pragma unroll
        for (int q = 0; q < 8; q++) s += part[q][t];
        g_partial[(b * NBLKP + blockIdx.x) * 7 + t] = s;
    }
}

// ---------------- energy reduce + intercept + output ----------------
__global__ void final_k(const float* __restrict__ valid,
                        const float* __restrict__ Wi1, const float* __restrict__ bi1,
                        const float* __restrict__ Wi2, const float* __restrict__ bi2,
                        float* __restrict__ out)
{
    int b = blockIdx.x, t = threadIdx.x;   // 128 threads
    __shared__ float red[128], energy[7], pooled[128], sv;
    for (int i = 0; i < 7; i++) {
        red[t] = g_partial[(b * NBLKP + t) * 7 + i]
               + g_partial[(b * NBLKP + t + 128) * 7 + i];
        __syncthreads();
        for (int o = 64; o; o >>= 1) {
            if (t < o) red[t] += red[t + o];
            __syncthreads();
        }
        if (t == 0) energy[i] = red[0];
        __syncthreads();
    }
    float s = 0.f;
    for (int j = 0; j < NN1; j++)
        s += g_x[(b * NN1 + j) * DD + t] * valid[b * NN1 + j];
    pooled[t] = s;
    __syncthreads();
    float a = bi1[t];
    for (int d = 0; d < 128; d++) a += pooled[d] * Wi1[d * 128 + t];
    red[t] = fmaxf(a, 0.f) * Wi2[t];
    __syncthreads();
    for (int o = 64; o; o >>= 1) {
        if (t < o) red[t] += red[t + o];
        __syncthreads();
    }
    if (t == 0) sv = 4.f / (1.f + expf(-(red[0] + bi2[0])));
    __syncthreads();
    if (t < 7) out[b * 7 + t] = energy[t] + sv / 7.f;
}

// ---------------- host ----------------
static inline float* symaddr(const void* sym)
{
    void* p = nullptr;
    cudaGetSymbolAddress(&p, sym);
    return (float*)p;
}

extern "C" void kernel_launch(void* const* d_in, const int* in_sizes, int n_in,
                              void* d_out, int out_size)
{
    (void)in_sizes; (void)n_in; (void)out_size;
    const float* h1      = (const float*)d_in[0];
    const float* adj1    = (const float*)d_in[1];
    const float* h2      = (const float*)d_in[2];
    const float* adj2    = (const float*)d_in[3];
    const float* A_int   = (const float*)d_in[4];
    const float* dmv     = (const float*)d_in[5];
    const float* valid   = (const float*)d_in[6];
    const float* W_embed = (const float*)d_in[7];
    const float* gW      = (const float*)d_in[8];
    const float* gWb     = (const float*)d_in[9];
    const float* gA      = (const float*)d_in[10];
    const float* gGateW  = (const float*)d_in[11];
    const float* gGateb  = (const float*)d_in[12];
    const float* WA1     = (const float*)d_in[13];
    const float* bA1     = (const float*)d_in[14];
    const float* WA2     = (const float*)d_in[15];
    const float* bA2     = (const float*)d_in[16];
    const float* WB1     = (const float*)d_in[17];
    const float* bB1     = (const float*)d_in[18];
    const float* WB2     = (const float*)d_in[19];
    const float* bB2     = (const float*)d_in[20];
    const float* Cw      = (const float*)d_in[21];
    const float* Wi1     = (const float*)d_in[22];
    const float* bi1     = (const float*)d_in[23];
    const float* Wi2     = (const float*)d_in[24];
    const float* bi2     = (const float*)d_in[25];
    float* out = (float*)d_out;

    float* p_wc = symaddr(g_wc);
    float* p_bc = symaddr(g_bc);

    prep<<<PB_E, 256>>>(h1, h2, adj1, adj2, A_int, dmv, W_embed, gW, gA, gWb);

    for (int l = 0; l < NL; l++) {
        gemm_hc<<<144, 256>>>(p_wc + l * DD * 256, p_bc + l * 256);
        stats_e<<<576, 256>>>();
        att_gate<<<576, 256>>>(gGateW + l * 256, gGateb + l);
    }

    u_gemms<<<1008, 256>>>(WA1, bA1, WB1, bB1);
    pair_energy<<<dim3(NBLKP, BB), 256>>>(WA2, bA2, WB2, bB2, Cw);
    final_k<<<BB, 128>>>(valid, Wi1, bi1, Wi2, bi2, out);
}